// round 4
// baseline (speedup 1.0000x reference)
#include <cuda_runtime.h>
#include <cstdint>
#include <cstring>
#include <math.h>

// ---------------------------------------------------------------------------
// Problem constants
// ---------------------------------------------------------------------------
#define BGR   512
#define NPG   64
#define CNUM  8
#define MPG   128
#define CN    256
#define CE    64
#define EPG   200            // MPG + CNUM + NPG

#define NE_NODES (BGR*MPG)        // 65536 br nodes
#define NE_EDGES (BGR*MPG*4)      // 262144 br edges
#define NN_NODES (BGR*NPG)        // 32768 nodes
#define NN_EDGES (BGR*EPG)        // 102400 edges

// output layout: out2 | ei | br | super_node
#define OFF_OUT2 0
#define OFF_EI   ((size_t)NN_NODES*CN)
#define OFF_BR   (OFF_EI + (size_t)NN_EDGES*CE)
#define OFF_SN   (OFF_BR + (size_t)NE_NODES*CE)

// ---------------------------------------------------------------------------
// Scratch (device globals: allocation-free)
// ---------------------------------------------------------------------------
__device__ float g_qE[(size_t)NE_NODES*CE];
__device__ float g_kE[(size_t)NE_NODES*CE];
__device__ float g_vE[(size_t)NE_NODES*CE];
__device__ float g_accE[(size_t)NE_NODES*CE];
__device__ float g_br1[(size_t)NE_NODES*CE];

__device__ float g_ei1[(size_t)NN_EDGES*CE];
__device__ float g_ef[(size_t)NN_EDGES*CN];
__device__ float g_qN[(size_t)NN_NODES*CN];
__device__ float g_kN[(size_t)NN_NODES*CN];
__device__ float g_vN[(size_t)NN_NODES*CN];
__device__ float g_accN[(size_t)NN_NODES*CN];
__device__ float g_out1[(size_t)NN_NODES*CN];

__device__ float g_bnsum[CN];
__device__ float g_bnsq[CN];
__device__ float g_mu[CN];
__device__ float g_rstd[CN];

// ---------------------------------------------------------------------------
// Fused QKV SGEMM with packed f32x2 FMA (unchanged from R3).
// ---------------------------------------------------------------------------
template<int TN>
__global__ void __launch_bounds__(256, 2) gemm_qkv(
    const float* __restrict__ A,
    const float* __restrict__ W0, const float* __restrict__ W1, const float* __restrict__ W2,
    float* __restrict__ C0, float* __restrict__ C1, float* __restrict__ C2,
    int M, int Nper, int K)
{
    constexpr int BK = 8;
    constexpr int NG = TN / 64;
    __shared__ float As[2][BK][128];
    __shared__ float Bs[2][BK][TN];

    const int nb  = Nper / TN;
    const int mat = blockIdx.x / nb;
    const int bn  = (blockIdx.x - mat * nb) * TN;
    const float* __restrict__ W = (mat == 0) ? W0 : ((mat == 1) ? W1 : W2);
    float* __restrict__ C       = (mat == 0) ? C0 : ((mat == 1) ? C1 : C2);
    const int bm = blockIdx.y * 128;
    const int t  = threadIdx.x;
    const int tx = t & 15, ty = t >> 4;

    const int ar = t >> 1, ac = (t & 1) * 4;
    const float* Ag = A + (size_t)(bm + ar) * K + ac;
    constexpr int BT = TN * BK / 4;
    const int brow = t / (TN / 4);
    const int bcol = (t % (TN / 4)) * 4;
    const float* Wg = W + (size_t)brow * Nper + bn + bcol;

    unsigned long long acc[8][2 * NG];
#pragma unroll
    for (int i = 0; i < 8; i++)
#pragma unroll
        for (int j = 0; j < 2 * NG; j++) acc[i][j] = 0ull;

    {
        float4 a = *reinterpret_cast<const float4*>(Ag);
        As[0][ac + 0][ar] = a.x; As[0][ac + 1][ar] = a.y;
        As[0][ac + 2][ar] = a.z; As[0][ac + 3][ar] = a.w;
        if (t < BT)
            *reinterpret_cast<float4*>(&Bs[0][brow][bcol]) =
                *reinterpret_cast<const float4*>(Wg);
    }
    __syncthreads();

    int buf = 0;
    for (int k0 = 0; k0 < K; k0 += BK) {
        float4 apre; float4 bpre;
        const bool nxt = (k0 + BK) < K;
        if (nxt) {
            apre = *reinterpret_cast<const float4*>(Ag + k0 + BK);
            if (t < BT)
                bpre = *reinterpret_cast<const float4*>(Wg + (size_t)(k0 + BK) * Nper);
        }
#pragma unroll
        for (int k = 0; k < BK; k++) {
            float4 a0 = *reinterpret_cast<const float4*>(&As[buf][k][ty * 4]);
            float4 a1 = *reinterpret_cast<const float4*>(&As[buf][k][64 + ty * 4]);
            float ar8[8] = {a0.x, a0.y, a0.z, a0.w, a1.x, a1.y, a1.z, a1.w};
            unsigned long long av[8];
#pragma unroll
            for (int i = 0; i < 8; i++)
                asm("mov.b64 %0, {%1, %1};" : "=l"(av[i]) : "f"(ar8[i]));
            unsigned long long bv[2 * NG];
#pragma unroll
            for (int g = 0; g < NG; g++) {
                ulonglong2 b2 = *reinterpret_cast<const ulonglong2*>(&Bs[buf][k][g * 64 + tx * 4]);
                bv[2 * g] = b2.x; bv[2 * g + 1] = b2.y;
            }
#pragma unroll
            for (int i = 0; i < 8; i++)
#pragma unroll
                for (int j = 0; j < 2 * NG; j++)
                    asm("fma.rn.f32x2 %0, %1, %2, %0;"
                        : "+l"(acc[i][j]) : "l"(av[i]), "l"(bv[j]));
        }
        if (nxt) {
            As[buf ^ 1][ac + 0][ar] = apre.x; As[buf ^ 1][ac + 1][ar] = apre.y;
            As[buf ^ 1][ac + 2][ar] = apre.z; As[buf ^ 1][ac + 3][ar] = apre.w;
            if (t < BT)
                *reinterpret_cast<float4*>(&Bs[buf ^ 1][brow][bcol]) = bpre;
            __syncthreads();
            buf ^= 1;
        }
    }

#pragma unroll
    for (int i = 0; i < 8; i++) {
        int row = bm + ((i < 4) ? (ty * 4 + i) : (64 + ty * 4 + (i - 4)));
        float* Crow = C + (size_t)row * Nper + bn;
#pragma unroll
        for (int g = 0; g < NG; g++) {
            float4 o;
            asm("mov.b64 {%0, %1}, %2;" : "=f"(o.x), "=f"(o.y) : "l"(acc[i][2 * g]));
            asm("mov.b64 {%0, %1}, %2;" : "=f"(o.z), "=f"(o.w) : "l"(acc[i][2 * g + 1]));
            *reinterpret_cast<float4*>(Crow + g * 64 + tx * 4) = o;
        }
    }
}

// ---------------------------------------------------------------------------
// Fused per-graph attention: logits + segmax + softmax + scatter + finalize
// + BN partial sums.  One block per graph; all intermediates in shared memory.
// Requires: 256 threads, H=4, C/32 channels per lane, 8 lanes per head.
// ---------------------------------------------------------------------------
template <int C, int H, int NODES, int EDGES, bool HAS_EF>
__global__ void __launch_bounds__(256) attn_fused(
    const float* __restrict__ q, const float* __restrict__ k,
    const float* __restrict__ v, const float* __restrict__ ef,
    const int* __restrict__ src, const int* __restrict__ dst,
    float* __restrict__ outbuf, float* __restrict__ bnsum, float* __restrict__ bnsq,
    float scale)
{
    constexpr int CPL = C / 32;          // channels per lane (8 or 2)
    constexpr int Oh  = C / H;
    extern __shared__ float sm[];
    float* sQ   = sm;                    // NODES*C  (reused as accumulator)
    float* sK   = sQ + NODES * C;        // NODES*C
    float* sLog = sK + NODES * C;        // EDGES*H  (logits, then weights)
    float* sMax = sLog + EDGES * H;      // NODES*H
    float* sSum = sMax + NODES * H;      // NODES*H

    const int g  = blockIdx.x;
    const int t  = threadIdx.x;
    const int nb = g * NODES;
    const int eb = g * EDGES;

    // stage q,k
    for (int i = t; i < NODES * C / 4; i += 256) {
        reinterpret_cast<float4*>(sQ)[i] = reinterpret_cast<const float4*>(q + (size_t)nb * C)[i];
        reinterpret_cast<float4*>(sK)[i] = reinterpret_cast<const float4*>(k + (size_t)nb * C)[i];
    }
    for (int i = t; i < NODES * H; i += 256) { sMax[i] = -INFINITY; sSum[i] = 0.f; }
    __syncthreads();

    const int warp = t >> 5, lane = t & 31;
    const int head = lane >> 3;          // 8 lanes per head

    // ---- phase 1: logits + per-(dst,head) max (smem atomics) ----
    for (int e = warp; e < EDGES; e += 8) {
        int s = src[eb + e] - nb, d = dst[eb + e] - nb;
        const float* qd = sQ + d * C + lane * CPL;
        const float* ks = sK + s * C + lane * CPL;
        float p = 0.f;
        if (HAS_EF) {
            const float* efe = ef + (size_t)(eb + e) * C + lane * CPL;
#pragma unroll
            for (int j = 0; j < CPL; j++) p += qd[j] * (ks[j] + efe[j]);
        } else {
#pragma unroll
            for (int j = 0; j < CPL; j++) p += qd[j] * ks[j];
        }
#pragma unroll
        for (int o = 4; o > 0; o >>= 1) p += __shfl_down_sync(0xffffffffu, p, o, 8);
        if ((lane & 7) == 0) {
            float l = p * scale;
            l = (l > 0.f) ? l : 0.2f * l;                 // leaky_relu 0.2
            sLog[e * H + head] = l;
            if (l >= 0.f) atomicMax((int*)&sMax[d * H + head], __float_as_int(l));
            else          atomicMin((unsigned int*)&sMax[d * H + head], __float_as_uint(l));
        }
    }
    __syncthreads();

    // ---- phase 1.5: weights + sums; zero accumulator (reuse sQ) ----
    for (int i = t; i < NODES * C / 4; i += 256)
        reinterpret_cast<float4*>(sQ)[i] = make_float4(0.f, 0.f, 0.f, 0.f);
    for (int i = t; i < EDGES * H; i += 256) {
        int d = dst[eb + i / H] - nb;
        int h = i % H;
        float w = expf(sLog[i] - sMax[d * H + h]);
        sLog[i] = w;
        atomicAdd(&sSum[d * H + h], w);
    }
    __syncthreads();

    // ---- phase 2: weighted scatter into smem accumulator ----
    // lane handles channels {lane, lane+32, ...}: conflict-free smem atomics,
    // coalesced global v/ef reads.
    for (int e = warp; e < EDGES; e += 8) {
        int s = src[eb + e] - nb, d = dst[eb + e] - nb;
        const float* vs  = v + (size_t)(nb + s) * C;
        const float* efe = HAS_EF ? (ef + (size_t)(eb + e) * C) : nullptr;
        float* ad = sQ + d * C;
        const float* wv = sLog + e * H;
#pragma unroll
        for (int j = 0; j < CPL; j++) {
            int c = lane + 32 * j;
            float w = wv[c / Oh];
            float vv = vs[c];
            if (HAS_EF) vv += efe[c];
            atomicAdd(&ad[c], w * vv);
        }
    }
    __syncthreads();

    // ---- phase 3: normalize, write out, BN partials ----
    // i = t + 256*m -> channel i%C == t%C is fixed per thread (256 % C == 0).
    const int c = t % C;
    float s1 = 0.f, s2 = 0.f;
    for (int i = t; i < NODES * C; i += 256) {
        int d = i / C;
        float o = sQ[i] / (sSum[d * H + c / Oh] + 1e-16f);
        outbuf[(size_t)nb * C + i] = o;
        s1 += o; s2 += o * o;
    }
    atomicAdd(&bnsum[c], s1);
    atomicAdd(&bnsq[c], s2);
}

// ---------------------------------------------------------------------------
// BN finalize / apply
// ---------------------------------------------------------------------------
__global__ void bn_final(const float* __restrict__ bnsum, const float* __restrict__ bnsq,
                         float* __restrict__ mu, float* __restrict__ rstd, int Nrows, int C) {
    int c = threadIdx.x;
    if (c < C) {
        float m = bnsum[c] / (float)Nrows;
        float v = bnsq[c] / (float)Nrows - m * m;
        mu[c] = m;
        rstd[c] = rsqrtf(v + 1e-5f);
    }
}

template <int C, bool SUB>
__global__ void bn_apply(const float* __restrict__ o, const float* __restrict__ res,
                         const float* __restrict__ mu, const float* __restrict__ rstd,
                         const float* __restrict__ g, const float* __restrict__ b,
                         float* __restrict__ out, int nelem) {
    int i = blockIdx.x * blockDim.x + threadIdx.x;
    if (i >= nelem) return;
    int c = i % C;
    float y = (o[i] - mu[c]) * rstd[c] * g[c] + b[c];
    y = fmaxf(y, 0.f);
    out[i] = SUB ? (res[i] - y) : (res[i] + y);
}

// ---------------------------------------------------------------------------
// BatchReversalToEdge
// ---------------------------------------------------------------------------
__global__ void to_edge(const float* __restrict__ br, float* __restrict__ ei) {
    int i = blockIdx.x * blockDim.x + threadIdx.x;
    if (i >= NN_EDGES * CE) return;
    int c = i % CE, row = i / CE;
    int g = row / EPG, r = row % EPG;
    float val;
    if (r < 2 * CNUM)             val = br[((size_t)g * MPG + (r >> 1)) * CE + c];
    else if (r < 2 * CNUM + NPG)  val = (c == 0) ? 1.f : 0.f;
    else                          val = br[((size_t)g * MPG + CNUM + (r - 2 * CNUM - NPG)) * CE + c];
    ei[i] = val;
}

__global__ void super_node_k(const float* __restrict__ out2, float* __restrict__ sn) {
    int i = blockIdx.x * blockDim.x + threadIdx.x;
    if (i >= BGR * CN) return;
    int g = i / CN, c = i % CN;
    sn[i] = out2[((size_t)g * NPG + NPG - 1) * CN + c];
}

// ---------------------------------------------------------------------------
// Host orchestration
// ---------------------------------------------------------------------------
static inline float* sym(const void* s) {
    void* p = nullptr;
    cudaGetSymbolAddress(&p, (const void*)s);
    return (float*)p;
}

#define SMEM_ATTN_N ((2*NPG*CN + EPG*4 + 2*NPG*4) * 4)     // ~136 KB
#define SMEM_ATTN_E ((2*MPG*CE + MPG*4*4 + 2*MPG*4) * 4)   // ~78 KB

extern "C" void kernel_launch(void* const* d_in, const int* in_sizes, int n_in,
                              void* d_out, int out_size) {
    (void)in_sizes; (void)n_in; (void)out_size;
    const float* x    = (const float*)d_in[0];
    const int*   eiN  = (const int*)d_in[1];
    const float* brf  = (const float*)d_in[2];
    const int*   eiE  = (const int*)d_in[3];
    const float* WqE1 = (const float*)d_in[4];
    const float* WkE1 = (const float*)d_in[5];
    const float* WvE1 = (const float*)d_in[6];
    const float* gE1  = (const float*)d_in[7];
    const float* bE1  = (const float*)d_in[8];
    const float* Wq1  = (const float*)d_in[9];
    const float* Wk1  = (const float*)d_in[10];
    const float* Wv1  = (const float*)d_in[11];
    const float* We1  = (const float*)d_in[12];
    const float* gN1  = (const float*)d_in[13];
    const float* bN1  = (const float*)d_in[14];
    const float* WqE2 = (const float*)d_in[15];
    const float* WkE2 = (const float*)d_in[16];
    const float* WvE2 = (const float*)d_in[17];
    const float* gE2  = (const float*)d_in[18];
    const float* bE2  = (const float*)d_in[19];
    const float* Wq2  = (const float*)d_in[20];
    const float* Wk2  = (const float*)d_in[21];
    const float* Wv2  = (const float*)d_in[22];
    const float* We2  = (const float*)d_in[23];
    const float* gN2  = (const float*)d_in[24];
    const float* bN2  = (const float*)d_in[25];

    float* out = (float*)d_out;
    float* out2_buf = out + OFF_OUT2;
    float* ei2_buf  = out + OFF_EI;
    float* br2_buf  = out + OFF_BR;
    float* sn_buf   = out + OFF_SN;

    float* qE   = sym(g_qE);   float* kE   = sym(g_kE);   float* vE  = sym(g_vE);
    float* accE = sym(g_accE); float* br1  = sym(g_br1);
    float* ei1  = sym(g_ei1);  float* ef   = sym(g_ef);
    float* qN   = sym(g_qN);   float* kN   = sym(g_kN);   float* vN  = sym(g_vN);
    float* accN = sym(g_accN); float* out1 = sym(g_out1);
    float* bnsum = sym(g_bnsum); float* bnsq = sym(g_bnsq);
    float* mu = sym(g_mu);       float* rstd = sym(g_rstd);

    const int* srcE = eiE;              const int* dstE = eiE + NE_EDGES;
    const int* srcN = eiN;              const int* dstN = eiN + NN_EDGES;

    const float scaleE = 0.25f;    // 1/sqrt(16)
    const float scaleN = 0.125f;   // 1/sqrt(64)

    static bool attr_done = false;
    if (!attr_done) {
        cudaFuncSetAttribute((const void*)attn_fused<CN, 4, NPG, EPG, true>,
                             cudaFuncAttributeMaxDynamicSharedMemorySize, SMEM_ATTN_N);
        cudaFuncSetAttribute((const void*)attn_fused<CE, 4, MPG, MPG * 4, false>,
                             cudaFuncAttributeMaxDynamicSharedMemorySize, SMEM_ATTN_E);
        attr_done = true;
    }

    dim3 qkvE(3 * (CE / 64), NE_NODES / 128);
    dim3 qkvN(3 * (CN / 128), NN_NODES / 128);
    dim3 efG(CN / 128, NN_EDGES / 128);

    // =============== E1: conv_E(br) -> bn -> relu -> +br ===============
    gemm_qkv<64><<<qkvE, 256>>>(brf, WqE1, WkE1, WvE1, qE, kE, vE, NE_NODES, CE, CE);
    cudaMemsetAsync(bnsum, 0, CN * 4);
    cudaMemsetAsync(bnsq, 0, CN * 4);
    attn_fused<CE, 4, MPG, MPG * 4, false><<<BGR, 256, SMEM_ATTN_E>>>(
        qE, kE, vE, nullptr, srcE, dstE, accE, bnsum, bnsq, scaleE);
    bn_final<<<1, 256>>>(bnsum, bnsq, mu, rstd, NE_NODES, CE);
    bn_apply<CE, false><<<(NE_NODES * CE) / 256, 256>>>(accE, brf, mu, rstd, gE1, bE1, br1, NE_NODES * CE);

    // =============== to_edge(br1) -> ei1, ef1 = ei1 @ We1 ===============
    to_edge<<<(NN_EDGES * CE) / 256, 256>>>(br1, ei1);
    gemm_qkv<128><<<efG, 256>>>(ei1, We1, We1, We1, ef, ef, ef, NN_EDGES, CN, CE);

    // =============== N1: conv_N(x, ef1) -> bn -> relu -> +x ===============
    gemm_qkv<128><<<qkvN, 256>>>(x, Wq1, Wk1, Wv1, qN, kN, vN, NN_NODES, CN, CN);
    cudaMemsetAsync(bnsum, 0, CN * 4);
    cudaMemsetAsync(bnsq, 0, CN * 4);
    attn_fused<CN, 4, NPG, EPG, true><<<BGR, 256, SMEM_ATTN_N>>>(
        qN, kN, vN, ef, srcN, dstN, accN, bnsum, bnsq, scaleN);
    bn_final<<<1, 256>>>(bnsum, bnsq, mu, rstd, NN_NODES, CN);
    bn_apply<CN, false><<<(NN_NODES * CN) / 256, 256>>>(accN, x, mu, rstd, gN1, bN1, out1, NN_NODES * CN);

    // =============== E2: conv_E(br1) -> bn -> relu; br2 = br1 - o ===============
    gemm_qkv<64><<<qkvE, 256>>>(br1, WqE2, WkE2, WvE2, qE, kE, vE, NE_NODES, CE, CE);
    cudaMemsetAsync(bnsum, 0, CN * 4);
    cudaMemsetAsync(bnsq, 0, CN * 4);
    attn_fused<CE, 4, MPG, MPG * 4, false><<<BGR, 256, SMEM_ATTN_E>>>(
        qE, kE, vE, nullptr, srcE, dstE, accE, bnsum, bnsq, scaleE);
    bn_final<<<1, 256>>>(bnsum, bnsq, mu, rstd, NE_NODES, CE);
    bn_apply<CE, true><<<(NE_NODES * CE) / 256, 256>>>(accE, br1, mu, rstd, gE2, bE2, br2_buf, NE_NODES * CE);

    // =============== to_edge(br2) -> ei2 (output), ef2 = ei2 @ We2 ===============
    to_edge<<<(NN_EDGES * CE) / 256, 256>>>(br2_buf, ei2_buf);
    gemm_qkv<128><<<efG, 256>>>(ei2_buf, We2, We2, We2, ef, ef, ef, NN_EDGES, CN, CE);

    // =============== N2: conv_N(out1, ef2) -> bn -> relu; out2 = out1 - o ===============
    gemm_qkv<128><<<qkvN, 256>>>(out1, Wq2, Wk2, Wv2, qN, kN, vN, NN_NODES, CN, CN);
    cudaMemsetAsync(bnsum, 0, CN * 4);
    cudaMemsetAsync(bnsq, 0, CN * 4);
    attn_fused<CN, 4, NPG, EPG, true><<<BGR, 256, SMEM_ATTN_N>>>(
        qN, kN, vN, ef, srcN, dstN, accN, bnsum, bnsq, scaleN);
    bn_final<<<1, 256>>>(bnsum, bnsq, mu, rstd, NN_NODES, CN);
    bn_apply<CN, true><<<(NN_NODES * CN) / 256, 256>>>(accN, out1, mu, rstd, gN2, bN2, out2_buf, NN_NODES * CN);

    // =============== super node ===============
    super_node_k<<<(BGR * CN) / 256, 256>>>(out2_buf, sn_buf);
}

// round 5
// speedup vs baseline: 1.5919x; 1.5919x over previous
#include <cuda_runtime.h>
#include <cstdint>
#include <cstring>
#include <math.h>

// ---------------------------------------------------------------------------
// Problem constants
// ---------------------------------------------------------------------------
#define BGR   512
#define NPG   64
#define CNUM  8
#define MPG   128
#define CN    256
#define CE    64
#define EPG   200            // MPG + CNUM + NPG

#define NE_NODES (BGR*MPG)        // 65536 br nodes
#define NE_EDGES (BGR*MPG*4)      // 262144 br edges
#define NN_NODES (BGR*NPG)        // 32768 nodes
#define NN_EDGES (BGR*EPG)        // 102400 edges

// output layout: out2 | ei | br | super_node
#define OFF_OUT2 0
#define OFF_EI   ((size_t)NN_NODES*CN)
#define OFF_BR   (OFF_EI + (size_t)NN_EDGES*CE)
#define OFF_SN   (OFF_BR + (size_t)NE_NODES*CE)

// ---------------------------------------------------------------------------
// Scratch (device globals: allocation-free)
// ---------------------------------------------------------------------------
__device__ float g_qE[(size_t)NE_NODES*CE];
__device__ float g_kE[(size_t)NE_NODES*CE];
__device__ float g_vE[(size_t)NE_NODES*CE];
__device__ float g_accE[(size_t)NE_NODES*CE];
__device__ float g_br1[(size_t)NE_NODES*CE];

__device__ float g_ei1[(size_t)NN_EDGES*CE];
__device__ float g_ef[(size_t)NN_EDGES*CN];
__device__ float g_qN[(size_t)NN_NODES*CN];
__device__ float g_kN[(size_t)NN_NODES*CN];
__device__ float g_vN[(size_t)NN_NODES*CN];
__device__ float g_accN[(size_t)NN_NODES*CN];
__device__ float g_out1[(size_t)NN_NODES*CN];

__device__ float g_bnpart[(size_t)BGR * 2 * CN];   // per-block BN partials
__device__ float g_mu[CN];
__device__ float g_rstd[CN];

// ---------------------------------------------------------------------------
// Fused QKV SGEMM with packed f32x2 FMA (unchanged from R3).
// ---------------------------------------------------------------------------
template<int TN>
__global__ void __launch_bounds__(256, 2) gemm_qkv(
    const float* __restrict__ A,
    const float* __restrict__ W0, const float* __restrict__ W1, const float* __restrict__ W2,
    float* __restrict__ C0, float* __restrict__ C1, float* __restrict__ C2,
    int M, int Nper, int K)
{
    constexpr int BK = 8;
    constexpr int NG = TN / 64;
    __shared__ float As[2][BK][128];
    __shared__ float Bs[2][BK][TN];

    const int nb  = Nper / TN;
    const int mat = blockIdx.x / nb;
    const int bn  = (blockIdx.x - mat * nb) * TN;
    const float* __restrict__ W = (mat == 0) ? W0 : ((mat == 1) ? W1 : W2);
    float* __restrict__ C       = (mat == 0) ? C0 : ((mat == 1) ? C1 : C2);
    const int bm = blockIdx.y * 128;
    const int t  = threadIdx.x;
    const int tx = t & 15, ty = t >> 4;

    const int ar = t >> 1, ac = (t & 1) * 4;
    const float* Ag = A + (size_t)(bm + ar) * K + ac;
    constexpr int BT = TN * BK / 4;
    const int brow = t / (TN / 4);
    const int bcol = (t % (TN / 4)) * 4;
    const float* Wg = W + (size_t)brow * Nper + bn + bcol;

    unsigned long long acc[8][2 * NG];
#pragma unroll
    for (int i = 0; i < 8; i++)
#pragma unroll
        for (int j = 0; j < 2 * NG; j++) acc[i][j] = 0ull;

    {
        float4 a = *reinterpret_cast<const float4*>(Ag);
        As[0][ac + 0][ar] = a.x; As[0][ac + 1][ar] = a.y;
        As[0][ac + 2][ar] = a.z; As[0][ac + 3][ar] = a.w;
        if (t < BT)
            *reinterpret_cast<float4*>(&Bs[0][brow][bcol]) =
                *reinterpret_cast<const float4*>(Wg);
    }
    __syncthreads();

    int buf = 0;
    for (int k0 = 0; k0 < K; k0 += BK) {
        float4 apre; float4 bpre;
        const bool nxt = (k0 + BK) < K;
        if (nxt) {
            apre = *reinterpret_cast<const float4*>(Ag + k0 + BK);
            if (t < BT)
                bpre = *reinterpret_cast<const float4*>(Wg + (size_t)(k0 + BK) * Nper);
        }
#pragma unroll
        for (int k = 0; k < BK; k++) {
            float4 a0 = *reinterpret_cast<const float4*>(&As[buf][k][ty * 4]);
            float4 a1 = *reinterpret_cast<const float4*>(&As[buf][k][64 + ty * 4]);
            float ar8[8] = {a0.x, a0.y, a0.z, a0.w, a1.x, a1.y, a1.z, a1.w};
            unsigned long long av[8];
#pragma unroll
            for (int i = 0; i < 8; i++)
                asm("mov.b64 %0, {%1, %1};" : "=l"(av[i]) : "f"(ar8[i]));
            unsigned long long bv[2 * NG];
#pragma unroll
            for (int g = 0; g < NG; g++) {
                ulonglong2 b2 = *reinterpret_cast<const ulonglong2*>(&Bs[buf][k][g * 64 + tx * 4]);
                bv[2 * g] = b2.x; bv[2 * g + 1] = b2.y;
            }
#pragma unroll
            for (int i = 0; i < 8; i++)
#pragma unroll
                for (int j = 0; j < 2 * NG; j++)
                    asm("fma.rn.f32x2 %0, %1, %2, %0;"
                        : "+l"(acc[i][j]) : "l"(av[i]), "l"(bv[j]));
        }
        if (nxt) {
            As[buf ^ 1][ac + 0][ar] = apre.x; As[buf ^ 1][ac + 1][ar] = apre.y;
            As[buf ^ 1][ac + 2][ar] = apre.z; As[buf ^ 1][ac + 3][ar] = apre.w;
            if (t < BT)
                *reinterpret_cast<float4*>(&Bs[buf ^ 1][brow][bcol]) = bpre;
            __syncthreads();
            buf ^= 1;
        }
    }

#pragma unroll
    for (int i = 0; i < 8; i++) {
        int row = bm + ((i < 4) ? (ty * 4 + i) : (64 + ty * 4 + (i - 4)));
        float* Crow = C + (size_t)row * Nper + bn;
#pragma unroll
        for (int g = 0; g < NG; g++) {
            float4 o;
            asm("mov.b64 {%0, %1}, %2;" : "=f"(o.x), "=f"(o.y) : "l"(acc[i][2 * g]));
            asm("mov.b64 {%0, %1}, %2;" : "=f"(o.z), "=f"(o.w) : "l"(acc[i][2 * g + 1]));
            *reinterpret_cast<float4*>(Crow + g * 64 + tx * 4) = o;
        }
    }
}

// ---------------------------------------------------------------------------
// Fused per-graph attention conv: CSR build + logits + softmax + aggregate +
// normalize + BN partials.  Block per graph, 256 threads, warp-per-dst-node.
// Tiny static smem; no global atomics; no memsets needed.
// H must be 4 (8 lanes per head).
// ---------------------------------------------------------------------------
template <int C, int H, int NODES, int EDGES, bool HAS_EF>
__global__ void __launch_bounds__(256) attn_conv(
    const float* __restrict__ q, const float* __restrict__ k,
    const float* __restrict__ v, const float* __restrict__ ef,
    const int* __restrict__ src, const int* __restrict__ dst,
    float* __restrict__ outbuf, float* __restrict__ bnpart, float scale)
{
    constexpr int Oh = C / H;        // head dim
    constexpr int JD = C / 32;       // channels per lane, layout B
    constexpr int JA = Oh / 8;       // channels per lane per head, layout A

    __shared__ int   sOff[NODES + 1];
    __shared__ int   sCur[NODES];
    __shared__ int   sAdj[EDGES];
    __shared__ float sW[EDGES * H];
    __shared__ float sSumW[8 * H];
    __shared__ float sBN[2 * C];

    const int g = blockIdx.x, t = threadIdx.x;
    const int nb = g * NODES, eb = g * EDGES;
    const int warp = t >> 5, lane = t & 31;

    // ---- CSR by dst (in smem) ----
    for (int i = t; i < NODES; i += 256) sCur[i] = 0;
    for (int i = t; i < 2 * C; i += 256) sBN[i] = 0.f;
    __syncthreads();
    for (int e = t; e < EDGES; e += 256) atomicAdd(&sCur[dst[eb + e] - nb], 1);
    __syncthreads();
    if (t == 0) {
        int run = 0;
        for (int i = 0; i < NODES; i++) { sOff[i] = run; run += sCur[i]; }
        sOff[NODES] = run;
    }
    __syncthreads();
    for (int i = t; i < NODES; i += 256) sCur[i] = sOff[i];
    __syncthreads();
    for (int e = t; e < EDGES; e += 256) {
        int d = dst[eb + e] - nb;
        sAdj[atomicAdd(&sCur[d], 1)] = e;
    }
    __syncthreads();

    const int h = lane >> 3, u = lane & 7;   // 8 lanes per head
    float s1[JD], s2[JD];
#pragma unroll
    for (int j = 0; j < JD; j++) { s1[j] = 0.f; s2[j] = 0.f; }

    for (int d = warp; d < NODES; d += 8) {
        const int e0 = sOff[d], e1 = sOff[d + 1];

        // q regs, layout A
        float qv[JA];
#pragma unroll
        for (int j = 0; j < JA; j++)
            qv[j] = q[(size_t)(nb + d) * C + h * Oh + u + 8 * j];

        // pass 1: logits (per head) + in-warp max
        float mx = -INFINITY;
        for (int ii = e0; ii < e1; ii++) {
            int e = sAdj[ii];
            int s = src[eb + e] - nb;
            const float* kr = k + (size_t)(nb + s) * C;
            const float* er = HAS_EF ? (ef + (size_t)(eb + e) * C) : nullptr;
            float p = 0.f;
#pragma unroll
            for (int j = 0; j < JA; j++) {
                int c = h * Oh + u + 8 * j;
                float kk = kr[c];
                if (HAS_EF) kk += er[c];
                p += qv[j] * kk;
            }
            p += __shfl_xor_sync(0xffffffffu, p, 1);
            p += __shfl_xor_sync(0xffffffffu, p, 2);
            p += __shfl_xor_sync(0xffffffffu, p, 4);
            float l = p * scale;
            l = (l > 0.f) ? l : 0.2f * l;           // leaky_relu 0.2
            if (u == 0) sW[e * H + h] = l;
            mx = fmaxf(mx, l);
        }
        __syncwarp();

        // pass 2: weights + per-head sum
        float sumh = 0.f;
        for (int ii = e0; ii < e1; ii++) {
            int e = sAdj[ii];
            float w = expf(sW[e * H + h] - mx);
            if (u == 0) sW[e * H + h] = w;
            sumh += w;
        }
        if (u == 0) sSumW[warp * H + h] = sumh;
        __syncwarp();

        // pass 3: accumulate w * (v[src] + ef), layout B
        float acc[JD];
#pragma unroll
        for (int j = 0; j < JD; j++) acc[j] = 0.f;
        for (int ii = e0; ii < e1; ii++) {
            int e = sAdj[ii];
            int s = src[eb + e] - nb;
            const float* vr = v + (size_t)(nb + s) * C;
            const float* er = HAS_EF ? (ef + (size_t)(eb + e) * C) : nullptr;
            const float* we = sW + e * H;
#pragma unroll
            for (int j = 0; j < JD; j++) {
                int c = lane + 32 * j;
                float vv = vr[c];
                if (HAS_EF) vv += er[c];
                acc[j] += we[c / Oh] * vv;
            }
        }

        // pass 4: normalize + write + BN partials
        float* orow = outbuf + (size_t)(nb + d) * C;
#pragma unroll
        for (int j = 0; j < JD; j++) {
            int c = lane + 32 * j;
            float o = acc[j] / (sSumW[warp * H + c / Oh] + 1e-16f);
            orow[c] = o;
            s1[j] += o; s2[j] += o * o;
        }
    }

    // block BN reduction
#pragma unroll
    for (int j = 0; j < JD; j++) {
        int c = lane + 32 * j;
        atomicAdd(&sBN[c], s1[j]);
        atomicAdd(&sBN[C + c], s2[j]);
    }
    __syncthreads();
    for (int i = t; i < 2 * C; i += 256)
        bnpart[(size_t)g * 2 * C + i] = sBN[i];
}

// ---------------------------------------------------------------------------
// BN stats reduce over per-block partials
// ---------------------------------------------------------------------------
template <int C>
__global__ void bn_final2(const float* __restrict__ part,
                          float* __restrict__ mu, float* __restrict__ rstd,
                          int nblocks, int Nrows) {
    constexpr int NSL = 1024 / C;
    __shared__ float rs[1024], rss[1024];
    int t = threadIdx.x;
    int c = t % C, sl = t / C;
    float s = 0.f, ss = 0.f;
    for (int b = sl; b < nblocks; b += NSL) {
        s  += part[(size_t)b * 2 * C + c];
        ss += part[(size_t)b * 2 * C + C + c];
    }
    rs[t] = s; rss[t] = ss;
    __syncthreads();
    if (sl == 0) {
        for (int i = 1; i < NSL; i++) { s += rs[i * C + c]; ss += rss[i * C + c]; }
        float m = s / (float)Nrows;
        float var = ss / (float)Nrows - m * m;
        mu[c] = m;
        rstd[c] = rsqrtf(var + 1e-5f);
    }
}

// relu(bn(o)) then residual (+ or -)
template <int C, bool SUB>
__global__ void bn_apply(const float* __restrict__ o, const float* __restrict__ res,
                         const float* __restrict__ mu, const float* __restrict__ rstd,
                         const float* __restrict__ g, const float* __restrict__ b,
                         float* __restrict__ out, int nelem) {
    int i = blockIdx.x * blockDim.x + threadIdx.x;
    if (i >= nelem) return;
    int c = i % C;
    float y = (o[i] - mu[c]) * rstd[c] * g[c] + b[c];
    y = fmaxf(y, 0.f);
    out[i] = SUB ? (res[i] - y) : (res[i] + y);
}

// ---------------------------------------------------------------------------
// BatchReversalToEdge
// ---------------------------------------------------------------------------
__global__ void to_edge(const float* __restrict__ br, float* __restrict__ ei) {
    int i = blockIdx.x * blockDim.x + threadIdx.x;
    if (i >= NN_EDGES * CE) return;
    int c = i % CE, row = i / CE;
    int g = row / EPG, r = row % EPG;
    float val;
    if (r < 2 * CNUM)             val = br[((size_t)g * MPG + (r >> 1)) * CE + c];
    else if (r < 2 * CNUM + NPG)  val = (c == 0) ? 1.f : 0.f;
    else                          val = br[((size_t)g * MPG + CNUM + (r - 2 * CNUM - NPG)) * CE + c];
    ei[i] = val;
}

__global__ void super_node_k(const float* __restrict__ out2, float* __restrict__ sn) {
    int i = blockIdx.x * blockDim.x + threadIdx.x;
    if (i >= BGR * CN) return;
    int g = i / CN, c = i % CN;
    sn[i] = out2[((size_t)g * NPG + NPG - 1) * CN + c];
}

// ---------------------------------------------------------------------------
// Host orchestration
// ---------------------------------------------------------------------------
static inline float* sym(const void* s) {
    void* p = nullptr;
    cudaGetSymbolAddress(&p, (const void*)s);
    return (float*)p;
}

extern "C" void kernel_launch(void* const* d_in, const int* in_sizes, int n_in,
                              void* d_out, int out_size) {
    (void)in_sizes; (void)n_in; (void)out_size;
    const float* x    = (const float*)d_in[0];
    const int*   eiN  = (const int*)d_in[1];
    const float* brf  = (const float*)d_in[2];
    const int*   eiE  = (const int*)d_in[3];
    const float* WqE1 = (const float*)d_in[4];
    const float* WkE1 = (const float*)d_in[5];
    const float* WvE1 = (const float*)d_in[6];
    const float* gE1  = (const float*)d_in[7];
    const float* bE1  = (const float*)d_in[8];
    const float* Wq1  = (const float*)d_in[9];
    const float* Wk1  = (const float*)d_in[10];
    const float* Wv1  = (const float*)d_in[11];
    const float* We1  = (const float*)d_in[12];
    const float* gN1  = (const float*)d_in[13];
    const float* bN1  = (const float*)d_in[14];
    const float* WqE2 = (const float*)d_in[15];
    const float* WkE2 = (const float*)d_in[16];
    const float* WvE2 = (const float*)d_in[17];
    const float* gE2  = (const float*)d_in[18];
    const float* bE2  = (const float*)d_in[19];
    const float* Wq2  = (const float*)d_in[20];
    const float* Wk2  = (const float*)d_in[21];
    const float* Wv2  = (const float*)d_in[22];
    const float* We2  = (const float*)d_in[23];
    const float* gN2  = (const float*)d_in[24];
    const float* bN2  = (const float*)d_in[25];

    float* out = (float*)d_out;
    float* out2_buf = out + OFF_OUT2;
    float* ei2_buf  = out + OFF_EI;
    float* br2_buf  = out + OFF_BR;
    float* sn_buf   = out + OFF_SN;

    float* qE   = sym(g_qE);   float* kE   = sym(g_kE);   float* vE  = sym(g_vE);
    float* accE = sym(g_accE); float* br1  = sym(g_br1);
    float* ei1  = sym(g_ei1);  float* ef   = sym(g_ef);
    float* qN   = sym(g_qN);   float* kN   = sym(g_kN);   float* vN  = sym(g_vN);
    float* accN = sym(g_accN); float* out1 = sym(g_out1);
    float* bnpart = sym(g_bnpart);
    float* mu = sym(g_mu);       float* rstd = sym(g_rstd);

    const int* srcE = eiE;              const int* dstE = eiE + NE_EDGES;
    const int* srcN = eiN;              const int* dstN = eiN + NN_EDGES;

    const float scaleE = 0.25f;    // 1/sqrt(16)
    const float scaleN = 0.125f;   // 1/sqrt(64)

    dim3 qkvE(3 * (CE / 64), NE_NODES / 128);
    dim3 qkvN(3 * (CN / 128), NN_NODES / 128);
    dim3 efG(CN / 128, NN_EDGES / 128);

    // =============== E1: conv_E(br) -> bn -> relu -> +br ===============
    gemm_qkv<64><<<qkvE, 256>>>(brf, WqE1, WkE1, WvE1, qE, kE, vE, NE_NODES, CE, CE);
    attn_conv<CE, 4, MPG, MPG * 4, false><<<BGR, 256>>>(
        qE, kE, vE, nullptr, srcE, dstE, accE, bnpart, scaleE);
    bn_final2<CE><<<1, 1024>>>(bnpart, mu, rstd, BGR, NE_NODES);
    bn_apply<CE, false><<<(NE_NODES * CE) / 256, 256>>>(accE, brf, mu, rstd, gE1, bE1, br1, NE_NODES * CE);

    // =============== to_edge(br1) -> ei1, ef1 = ei1 @ We1 ===============
    to_edge<<<(NN_EDGES * CE) / 256, 256>>>(br1, ei1);
    gemm_qkv<128><<<efG, 256>>>(ei1, We1, We1, We1, ef, ef, ef, NN_EDGES, CN, CE);

    // =============== N1: conv_N(x, ef1) -> bn -> relu -> +x ===============
    gemm_qkv<128><<<qkvN, 256>>>(x, Wq1, Wk1, Wv1, qN, kN, vN, NN_NODES, CN, CN);
    attn_conv<CN, 4, NPG, EPG, true><<<BGR, 256>>>(
        qN, kN, vN, ef, srcN, dstN, accN, bnpart, scaleN);
    bn_final2<CN><<<1, 1024>>>(bnpart, mu, rstd, BGR, NN_NODES);
    bn_apply<CN, false><<<(NN_NODES * CN) / 256, 256>>>(accN, x, mu, rstd, gN1, bN1, out1, NN_NODES * CN);

    // =============== E2: conv_E(br1) -> bn -> relu; br2 = br1 - o ===============
    gemm_qkv<64><<<qkvE, 256>>>(br1, WqE2, WkE2, WvE2, qE, kE, vE, NE_NODES, CE, CE);
    attn_conv<CE, 4, MPG, MPG * 4, false><<<BGR, 256>>>(
        qE, kE, vE, nullptr, srcE, dstE, accE, bnpart, scaleE);
    bn_final2<CE><<<1, 1024>>>(bnpart, mu, rstd, BGR, NE_NODES);
    bn_apply<CE, true><<<(NE_NODES * CE) / 256, 256>>>(accE, br1, mu, rstd, gE2, bE2, br2_buf, NE_NODES * CE);

    // =============== to_edge(br2) -> ei2 (output), ef2 = ei2 @ We2 ===============
    to_edge<<<(NN_EDGES * CE) / 256, 256>>>(br2_buf, ei2_buf);
    gemm_qkv<128><<<efG, 256>>>(ei2_buf, We2, We2, We2, ef, ef, ef, NN_EDGES, CN, CE);

    // =============== N2: conv_N(out1, ef2) -> bn -> relu; out2 = out1 - o ===============
    gemm_qkv<128><<<qkvN, 256>>>(out1, Wq2, Wk2, Wv2, qN, kN, vN, NN_NODES, CN, CN);
    attn_conv<CN, 4, NPG, EPG, true><<<BGR, 256>>>(
        qN, kN, vN, ef, srcN, dstN, accN, bnpart, scaleN);
    bn_final2<CN><<<1, 1024>>>(bnpart, mu, rstd, BGR, NN_NODES);
    bn_apply<CN, true><<<(NN_NODES * CN) / 256, 256>>>(accN, out1, mu, rstd, gN2, bN2, out2_buf, NN_NODES * CN);

    // =============== super node ===============
    super_node_k<<<(BGR * CN) / 256, 256>>>(out2_buf, sn_buf);
}

// round 6
// speedup vs baseline: 1.6222x; 1.0190x over previous
#include <cuda_runtime.h>
#include <cstdint>
#include <cstring>
#include <math.h>

// ---------------------------------------------------------------------------
// Problem constants
// ---------------------------------------------------------------------------
#define BGR   512
#define NPG   64
#define CNUM  8
#define MPG   128
#define CN    256
#define CE    64
#define EPG   200            // MPG + CNUM + NPG

#define NE_NODES (BGR*MPG)        // 65536 br nodes
#define NE_EDGES (BGR*MPG*4)      // 262144 br edges
#define NN_NODES (BGR*NPG)        // 32768 nodes
#define NN_EDGES (BGR*EPG)        // 102400 edges

// output layout: out2 | ei | br | super_node
#define OFF_OUT2 0
#define OFF_EI   ((size_t)NN_NODES*CN)
#define OFF_BR   (OFF_EI + (size_t)NN_EDGES*CE)
#define OFF_SN   (OFF_BR + (size_t)NE_NODES*CE)

// ---------------------------------------------------------------------------
// Scratch (device globals: allocation-free)
// ---------------------------------------------------------------------------
__device__ float g_qE[(size_t)NE_NODES*CE];
__device__ float g_kE[(size_t)NE_NODES*CE];
__device__ float g_vE[(size_t)NE_NODES*CE];
__device__ float g_accE[(size_t)NE_NODES*CE];
__device__ float g_br1[(size_t)NE_NODES*CE];

__device__ float g_efbr[(size_t)NE_NODES*CN];      // br @ We (unique ef rows)
__device__ float g_qN[(size_t)NN_NODES*CN];
__device__ float g_kN[(size_t)NN_NODES*CN];
__device__ float g_vN[(size_t)NN_NODES*CN];
__device__ float g_accN[(size_t)NN_NODES*CN];
__device__ float g_out1[(size_t)NN_NODES*CN];

__device__ float g_bnpart[(size_t)BGR * 2 * CN];   // per-block BN partials
__device__ float g_mu[CN];
__device__ float g_rstd[CN];

// ---------------------------------------------------------------------------
// Fused QKV SGEMM with packed f32x2 FMA.
// ---------------------------------------------------------------------------
template<int TN>
__global__ void __launch_bounds__(256, 2) gemm_qkv(
    const float* __restrict__ A,
    const float* __restrict__ W0, const float* __restrict__ W1, const float* __restrict__ W2,
    float* __restrict__ C0, float* __restrict__ C1, float* __restrict__ C2,
    int M, int Nper, int K)
{
    constexpr int BK = 8;
    constexpr int NG = TN / 64;
    __shared__ float As[2][BK][128];
    __shared__ float Bs[2][BK][TN];

    const int nb  = Nper / TN;
    const int mat = blockIdx.x / nb;
    const int bn  = (blockIdx.x - mat * nb) * TN;
    const float* __restrict__ W = (mat == 0) ? W0 : ((mat == 1) ? W1 : W2);
    float* __restrict__ C       = (mat == 0) ? C0 : ((mat == 1) ? C1 : C2);
    const int bm = blockIdx.y * 128;
    const int t  = threadIdx.x;
    const int tx = t & 15, ty = t >> 4;

    const int ar = t >> 1, ac = (t & 1) * 4;
    const float* Ag = A + (size_t)(bm + ar) * K + ac;
    constexpr int BT = TN * BK / 4;
    const int brow = t / (TN / 4);
    const int bcol = (t % (TN / 4)) * 4;
    const float* Wg = W + (size_t)brow * Nper + bn + bcol;

    unsigned long long acc[8][2 * NG];
#pragma unroll
    for (int i = 0; i < 8; i++)
#pragma unroll
        for (int j = 0; j < 2 * NG; j++) acc[i][j] = 0ull;

    {
        float4 a = *reinterpret_cast<const float4*>(Ag);
        As[0][ac + 0][ar] = a.x; As[0][ac + 1][ar] = a.y;
        As[0][ac + 2][ar] = a.z; As[0][ac + 3][ar] = a.w;
        if (t < BT)
            *reinterpret_cast<float4*>(&Bs[0][brow][bcol]) =
                *reinterpret_cast<const float4*>(Wg);
    }
    __syncthreads();

    int buf = 0;
    for (int k0 = 0; k0 < K; k0 += BK) {
        float4 apre; float4 bpre;
        const bool nxt = (k0 + BK) < K;
        if (nxt) {
            apre = *reinterpret_cast<const float4*>(Ag + k0 + BK);
            if (t < BT)
                bpre = *reinterpret_cast<const float4*>(Wg + (size_t)(k0 + BK) * Nper);
        }
#pragma unroll
        for (int k = 0; k < BK; k++) {
            float4 a0 = *reinterpret_cast<const float4*>(&As[buf][k][ty * 4]);
            float4 a1 = *reinterpret_cast<const float4*>(&As[buf][k][64 + ty * 4]);
            float ar8[8] = {a0.x, a0.y, a0.z, a0.w, a1.x, a1.y, a1.z, a1.w};
            unsigned long long av[8];
#pragma unroll
            for (int i = 0; i < 8; i++)
                asm("mov.b64 %0, {%1, %1};" : "=l"(av[i]) : "f"(ar8[i]));
            unsigned long long bv[2 * NG];
#pragma unroll
            for (int g = 0; g < NG; g++) {
                ulonglong2 b2 = *reinterpret_cast<const ulonglong2*>(&Bs[buf][k][g * 64 + tx * 4]);
                bv[2 * g] = b2.x; bv[2 * g + 1] = b2.y;
            }
#pragma unroll
            for (int i = 0; i < 8; i++)
#pragma unroll
                for (int j = 0; j < 2 * NG; j++)
                    asm("fma.rn.f32x2 %0, %1, %2, %0;"
                        : "+l"(acc[i][j]) : "l"(av[i]), "l"(bv[j]));
        }
        if (nxt) {
            As[buf ^ 1][ac + 0][ar] = apre.x; As[buf ^ 1][ac + 1][ar] = apre.y;
            As[buf ^ 1][ac + 2][ar] = apre.z; As[buf ^ 1][ac + 3][ar] = apre.w;
            if (t < BT)
                *reinterpret_cast<float4*>(&Bs[buf ^ 1][brow][bcol]) = bpre;
            __syncthreads();
            buf ^= 1;
        }
    }

#pragma unroll
    for (int i = 0; i < 8; i++) {
        int row = bm + ((i < 4) ? (ty * 4 + i) : (64 + ty * 4 + (i - 4)));
        float* Crow = C + (size_t)row * Nper + bn;
#pragma unroll
        for (int g = 0; g < NG; g++) {
            float4 o;
            asm("mov.b64 {%0, %1}, %2;" : "=f"(o.x), "=f"(o.y) : "l"(acc[i][2 * g]));
            asm("mov.b64 {%0, %1}, %2;" : "=f"(o.z), "=f"(o.w) : "l"(acc[i][2 * g + 1]));
            *reinterpret_cast<float4*>(Crow + g * 64 + tx * 4) = o;
        }
    }
}

// ef row for local edge index e in graph g (N-side only):
// rows [0,16): efbr row 2*CNUM dup; [16,80): one-hot -> We row 0; else br row e-72.
__device__ __forceinline__ const float* ef_row(const float* __restrict__ efbr,
                                               const float* __restrict__ we0,
                                               int g, int e) {
    if (e < 2 * CNUM)       return efbr + ((size_t)g * MPG + (e >> 1)) * CN;
    if (e < 2 * CNUM + NPG) return we0;
    return efbr + ((size_t)g * MPG + e - (CNUM + NPG)) * CN;
}

// ---------------------------------------------------------------------------
// Fused per-graph attention conv (CSR in smem, warp-per-dst-node).
// ---------------------------------------------------------------------------
template <int C, int H, int NODES, int EDGES, bool HAS_EF>
__global__ void __launch_bounds__(256) attn_conv(
    const float* __restrict__ q, const float* __restrict__ k,
    const float* __restrict__ v,
    const float* __restrict__ efbr, const float* __restrict__ we0,
    const int* __restrict__ src, const int* __restrict__ dst,
    float* __restrict__ outbuf, float* __restrict__ bnpart, float scale)
{
    constexpr int Oh = C / H;
    constexpr int JD = C / 32;
    constexpr int JA = Oh / 8;

    __shared__ int   sOff[NODES + 1];
    __shared__ int   sCur[NODES];
    __shared__ int   sAdj[EDGES];
    __shared__ float sW[EDGES * H];
    __shared__ float sSumW[8 * H];
    __shared__ float sBN[2 * C];

    const int g = blockIdx.x, t = threadIdx.x;
    const int nb = g * NODES, eb = g * EDGES;
    const int warp = t >> 5, lane = t & 31;

    for (int i = t; i < NODES; i += 256) sCur[i] = 0;
    for (int i = t; i < 2 * C; i += 256) sBN[i] = 0.f;
    __syncthreads();
    for (int e = t; e < EDGES; e += 256) atomicAdd(&sCur[dst[eb + e] - nb], 1);
    __syncthreads();
    if (t == 0) {
        int run = 0;
        for (int i = 0; i < NODES; i++) { sOff[i] = run; run += sCur[i]; }
        sOff[NODES] = run;
    }
    __syncthreads();
    for (int i = t; i < NODES; i += 256) sCur[i] = sOff[i];
    __syncthreads();
    for (int e = t; e < EDGES; e += 256) {
        int d = dst[eb + e] - nb;
        sAdj[atomicAdd(&sCur[d], 1)] = e;
    }
    __syncthreads();

    const int h = lane >> 3, u = lane & 7;
    float s1[JD], s2[JD];
#pragma unroll
    for (int j = 0; j < JD; j++) { s1[j] = 0.f; s2[j] = 0.f; }

    for (int d = warp; d < NODES; d += 8) {
        const int e0 = sOff[d], e1 = sOff[d + 1];

        float qv[JA];
#pragma unroll
        for (int j = 0; j < JA; j++)
            qv[j] = q[(size_t)(nb + d) * C + h * Oh + u + 8 * j];

        float mx = -INFINITY;
        for (int ii = e0; ii < e1; ii++) {
            int e = sAdj[ii];
            int s = src[eb + e] - nb;
            const float* kr = k + (size_t)(nb + s) * C;
            const float* er = HAS_EF ? ef_row(efbr, we0, g, e) : nullptr;
            float p = 0.f;
#pragma unroll
            for (int j = 0; j < JA; j++) {
                int c = h * Oh + u + 8 * j;
                float kk = kr[c];
                if (HAS_EF) kk += er[c];
                p += qv[j] * kk;
            }
            p += __shfl_xor_sync(0xffffffffu, p, 1);
            p += __shfl_xor_sync(0xffffffffu, p, 2);
            p += __shfl_xor_sync(0xffffffffu, p, 4);
            float l = p * scale;
            l = (l > 0.f) ? l : 0.2f * l;
            if (u == 0) sW[e * H + h] = l;
            mx = fmaxf(mx, l);
        }
        __syncwarp();

        float sumh = 0.f;
        for (int ii = e0; ii < e1; ii++) {
            int e = sAdj[ii];
            float w = expf(sW[e * H + h] - mx);
            if (u == 0) sW[e * H + h] = w;
            sumh += w;
        }
        if (u == 0) sSumW[warp * H + h] = sumh;
        __syncwarp();

        float acc[JD];
#pragma unroll
        for (int j = 0; j < JD; j++) acc[j] = 0.f;
        for (int ii = e0; ii < e1; ii++) {
            int e = sAdj[ii];
            int s = src[eb + e] - nb;
            const float* vr = v + (size_t)(nb + s) * C;
            const float* er = HAS_EF ? ef_row(efbr, we0, g, e) : nullptr;
            const float* we = sW + e * H;
#pragma unroll
            for (int j = 0; j < JD; j++) {
                int c = lane + 32 * j;
                float vv = vr[c];
                if (HAS_EF) vv += er[c];
                acc[j] += we[c / Oh] * vv;
            }
        }

        float* orow = outbuf + (size_t)(nb + d) * C;
#pragma unroll
        for (int j = 0; j < JD; j++) {
            int c = lane + 32 * j;
            float o = acc[j] / (sSumW[warp * H + c / Oh] + 1e-16f);
            orow[c] = o;
            s1[j] += o; s2[j] += o * o;
        }
    }

#pragma unroll
    for (int j = 0; j < JD; j++) {
        int c = lane + 32 * j;
        atomicAdd(&sBN[c], s1[j]);
        atomicAdd(&sBN[C + c], s2[j]);
    }
    __syncthreads();
    for (int i = t; i < 2 * C; i += 256)
        bnpart[(size_t)g * 2 * C + i] = sBN[i];
}

// ---------------------------------------------------------------------------
// BN stats reduce over per-block partials
// ---------------------------------------------------------------------------
template <int C>
__global__ void bn_final2(const float* __restrict__ part,
                          float* __restrict__ mu, float* __restrict__ rstd,
                          int nblocks, int Nrows) {
    constexpr int NSL = 1024 / C;
    __shared__ float rs[1024], rss[1024];
    int t = threadIdx.x;
    int c = t % C, sl = t / C;
    float s = 0.f, ss = 0.f;
    for (int b = sl; b < nblocks; b += NSL) {
        s  += part[(size_t)b * 2 * C + c];
        ss += part[(size_t)b * 2 * C + C + c];
    }
    rs[t] = s; rss[t] = ss;
    __syncthreads();
    if (sl == 0) {
        for (int i = 1; i < NSL; i++) { s += rs[i * C + c]; ss += rss[i * C + c]; }
        float m = s / (float)Nrows;
        float var = ss / (float)Nrows - m * m;
        mu[c] = m;
        rstd[c] = rsqrtf(var + 1e-5f);
    }
}

// relu(bn(o)) then residual (+ or -)
template <int C, bool SUB>
__global__ void bn_apply(const float* __restrict__ o, const float* __restrict__ res,
                         const float* __restrict__ mu, const float* __restrict__ rstd,
                         const float* __restrict__ g, const float* __restrict__ b,
                         float* __restrict__ out, int nelem) {
    int i = blockIdx.x * blockDim.x + threadIdx.x;
    if (i >= nelem) return;
    int c = i % C;
    float y = (o[i] - mu[c]) * rstd[c] * g[c] + b[c];
    y = fmaxf(y, 0.f);
    out[i] = SUB ? (res[i] - y) : (res[i] + y);
}

// E2 variant: also scatter br2 rows into ei2 (dup/tail regions of to_edge)
__global__ void bn_apply_toedge(const float* __restrict__ o, const float* __restrict__ res,
                                const float* __restrict__ mu, const float* __restrict__ rstd,
                                const float* __restrict__ gg, const float* __restrict__ bb,
                                float* __restrict__ brout, float* __restrict__ ei) {
    int i = blockIdx.x * blockDim.x + threadIdx.x;
    if (i >= NE_NODES * CE) return;
    int c = i % CE;
    int row = i / CE;
    int g = row / MPG, r = row % MPG;
    float y = (o[i] - mu[c]) * rstd[c] * gg[c] + bb[c];
    y = fmaxf(y, 0.f);
    float val = res[i] - y;
    brout[i] = val;
    size_t eib = (size_t)g * EPG;
    if (r < CNUM) {
        ei[(eib + 2 * r) * CE + c]     = val;
        ei[(eib + 2 * r + 1) * CE + c] = val;
    } else {
        ei[(eib + r + (CNUM + NPG)) * CE + c] = val;
    }
}

// N2 variant: also extract super node rows
__global__ void bn_apply_sn(const float* __restrict__ o, const float* __restrict__ res,
                            const float* __restrict__ mu, const float* __restrict__ rstd,
                            const float* __restrict__ gg, const float* __restrict__ bb,
                            float* __restrict__ out, float* __restrict__ sn) {
    int i = blockIdx.x * blockDim.x + threadIdx.x;
    if (i >= NN_NODES * CN) return;
    int c = i % CN;
    int row = i / CN;
    float y = (o[i] - mu[c]) * rstd[c] * gg[c] + bb[c];
    y = fmaxf(y, 0.f);
    float val = res[i] - y;
    out[i] = val;
    if ((row % NPG) == NPG - 1) sn[(size_t)(row / NPG) * CN + c] = val;
}

// constant one-hot block of ei2 (independent of all other work)
__global__ void onehot_fill(float* __restrict__ ei) {
    int i = blockIdx.x * blockDim.x + threadIdx.x;
    if (i >= BGR * NPG * CE) return;
    int c = i % CE;
    int row = i / CE;
    int g = row / NPG, rr = row % NPG;
    ei[((size_t)g * EPG + 2 * CNUM + rr) * CE + c] = (c == 0) ? 1.f : 0.f;
}

// ---------------------------------------------------------------------------
// Host orchestration
// ---------------------------------------------------------------------------
static inline float* sym(const void* s) {
    void* p = nullptr;
    cudaGetSymbolAddress(&p, (const void*)s);
    return (float*)p;
}

extern "C" void kernel_launch(void* const* d_in, const int* in_sizes, int n_in,
                              void* d_out, int out_size) {
    (void)in_sizes; (void)n_in; (void)out_size;
    const float* x    = (const float*)d_in[0];
    const int*   eiN  = (const int*)d_in[1];
    const float* brf  = (const float*)d_in[2];
    const int*   eiE  = (const int*)d_in[3];
    const float* WqE1 = (const float*)d_in[4];
    const float* WkE1 = (const float*)d_in[5];
    const float* WvE1 = (const float*)d_in[6];
    const float* gE1  = (const float*)d_in[7];
    const float* bE1  = (const float*)d_in[8];
    const float* Wq1  = (const float*)d_in[9];
    const float* Wk1  = (const float*)d_in[10];
    const float* Wv1  = (const float*)d_in[11];
    const float* We1  = (const float*)d_in[12];
    const float* gN1  = (const float*)d_in[13];
    const float* bN1  = (const float*)d_in[14];
    const float* WqE2 = (const float*)d_in[15];
    const float* WkE2 = (const float*)d_in[16];
    const float* WvE2 = (const float*)d_in[17];
    const float* gE2  = (const float*)d_in[18];
    const float* bE2  = (const float*)d_in[19];
    const float* Wq2  = (const float*)d_in[20];
    const float* Wk2  = (const float*)d_in[21];
    const float* Wv2  = (const float*)d_in[22];
    const float* We2  = (const float*)d_in[23];
    const float* gN2  = (const float*)d_in[24];
    const float* bN2  = (const float*)d_in[25];

    float* out = (float*)d_out;
    float* out2_buf = out + OFF_OUT2;
    float* ei2_buf  = out + OFF_EI;
    float* br2_buf  = out + OFF_BR;
    float* sn_buf   = out + OFF_SN;

    float* qE   = sym(g_qE);   float* kE   = sym(g_kE);   float* vE  = sym(g_vE);
    float* accE = sym(g_accE); float* br1  = sym(g_br1);
    float* efbr = sym(g_efbr);
    float* qN   = sym(g_qN);   float* kN   = sym(g_kN);   float* vN  = sym(g_vN);
    float* accN = sym(g_accN); float* out1 = sym(g_out1);
    float* bnpart = sym(g_bnpart);
    float* mu = sym(g_mu);       float* rstd = sym(g_rstd);

    const int* srcE = eiE;              const int* dstE = eiE + NE_EDGES;
    const int* srcN = eiN;              const int* dstN = eiN + NN_EDGES;

    const float scaleE = 0.25f;    // 1/sqrt(16)
    const float scaleN = 0.125f;   // 1/sqrt(64)

    dim3 qkvE(3 * (CE / 64), NE_NODES / 128);
    dim3 qkvN(3 * (CN / 128), NN_NODES / 128);
    dim3 efG(CN / 128, NE_NODES / 128);       // efbr = br @ We : 65536 x 256, K=64

    // constant part of ei2 — independent, do it first
    onehot_fill<<<(BGR * NPG * CE) / 256, 256>>>(ei2_buf);

    // =============== E1: conv_E(br) -> bn -> relu -> +br ===============
    gemm_qkv<64><<<qkvE, 256>>>(brf, WqE1, WkE1, WvE1, qE, kE, vE, NE_NODES, CE, CE);
    attn_conv<CE, 4, MPG, MPG * 4, false><<<BGR, 256>>>(
        qE, kE, vE, nullptr, nullptr, srcE, dstE, accE, bnpart, scaleE);
    bn_final2<CE><<<1, 1024>>>(bnpart, mu, rstd, BGR, NE_NODES);
    bn_apply<CE, false><<<(NE_NODES * CE) / 256, 256>>>(accE, brf, mu, rstd, gE1, bE1, br1, NE_NODES * CE);

    // =============== efbr1 = br1 @ We1 (unique ef rows) ===============
    gemm_qkv<128><<<efG, 256>>>(br1, We1, We1, We1, efbr, efbr, efbr, NE_NODES, CN, CE);

    // =============== N1: conv_N(x, ef1) -> bn -> relu -> +x ===============
    gemm_qkv<128><<<qkvN, 256>>>(x, Wq1, Wk1, Wv1, qN, kN, vN, NN_NODES, CN, CN);
    attn_conv<CN, 4, NPG, EPG, true><<<BGR, 256>>>(
        qN, kN, vN, efbr, We1, srcN, dstN, accN, bnpart, scaleN);
    bn_final2<CN><<<1, 1024>>>(bnpart, mu, rstd, BGR, NN_NODES);
    bn_apply<CN, false><<<(NN_NODES * CN) / 256, 256>>>(accN, x, mu, rstd, gN1, bN1, out1, NN_NODES * CN);

    // =============== E2: conv_E(br1) -> bn -> relu; br2 = br1 - o (+ ei2 scatter) ===============
    gemm_qkv<64><<<qkvE, 256>>>(br1, WqE2, WkE2, WvE2, qE, kE, vE, NE_NODES, CE, CE);
    attn_conv<CE, 4, MPG, MPG * 4, false><<<BGR, 256>>>(
        qE, kE, vE, nullptr, nullptr, srcE, dstE, accE, bnpart, scaleE);
    bn_final2<CE><<<1, 1024>>>(bnpart, mu, rstd, BGR, NE_NODES);
    bn_apply_toedge<<<(NE_NODES * CE) / 256, 256>>>(accE, br1, mu, rstd, gE2, bE2, br2_buf, ei2_buf);

    // =============== efbr2 = br2 @ We2 ===============
    gemm_qkv<128><<<efG, 256>>>(br2_buf, We2, We2, We2, efbr, efbr, efbr, NE_NODES, CN, CE);

    // =============== N2: conv_N(out1, ef2) -> bn -> relu; out2 = out1 - o (+ super node) ===============
    gemm_qkv<128><<<qkvN, 256>>>(out1, Wq2, Wk2, Wv2, qN, kN, vN, NN_NODES, CN, CN);
    attn_conv<CN, 4, NPG, EPG, true><<<BGR, 256>>>(
        qN, kN, vN, efbr, We2, srcN, dstN, accN, bnpart, scaleN);
    bn_final2<CN><<<1, 1024>>>(bnpart, mu, rstd, BGR, NN_NODES);
    bn_apply_sn<<<(NN_NODES * CN) / 256, 256>>>(accN, out1, mu, rstd, gN2, bN2, out2_buf, sn_buf);
}